// round 13
// baseline (speedup 1.0000x reference)
#include <cuda_runtime.h>
#include <math.h>

#define VOCABN   10003
#define NITEMS   10000
#define PADTOK   10000
#define NPOS     512
#define SEQLEN   128
#define NTHREADS 256

// ---------------------------------------------------------------------------
// helpers
// ---------------------------------------------------------------------------
__device__ __forceinline__ float tanh_unused(float x);  // (removed scalar path)

__device__ __forceinline__ float rcp_fast(float x)
{
    float y;
    asm("rcp.approx.f32 %0, %1;" : "=f"(y) : "f"(x));
    return y;
}

// pack two f32 -> f16x2 (d.hi = a, d.lo = b)
#define F32x2_TO_H2(d, hi, lo) \
    asm("cvt.rn.f16x2.f32 %0, %1, %2;" : "=r"(d) : "f"(hi), "f"(lo))

// unpack f16x2 -> two f32 (s0 = lo, s1 = hi)
#define H2_TO_F32x2(s0, s1, h) \
    asm("{\n\t.reg .b16 lo, hi;\n\t" \
        "mov.b32 {lo, hi}, %2;\n\t" \
        "cvt.f32.f16 %0, lo;\n\t" \
        "cvt.f32.f16 %1, hi;\n\t}" \
        : "=f"(s0), "=f"(s1) : "r"(h))

#define HMUL2(d, a, b) \
    asm("mul.f16x2 %0, %1, %2;" : "=r"(d) : "r"(a), "r"(b))
#define HFMA2(d, a, b, c) \
    asm("fma.rn.f16x2 %0, %1, %2, %3;" : "=r"(d) : "r"(a), "r"(b), "r"(c))
#define HTANH2(d, a) \
    asm("tanh.approx.f16x2 %0, %1;" : "=r"(d) : "r"(a))

// ---------------------------------------------------------------------------
// Fully fused kernel: one block per (b, t) position.
//  - in-block int64/int32 token decode (warp-0 ballot probe)
//  - inline 1/pop_biases via rcp.approx (+ div_no_nan zero guard)
//  - z-chain + accumulate in fp32; gelu cubic + tanh + z*th in f16x2
//    (HFMA2 rt2 = real 2x fma-pipe throughput; tanh.f16x2 = 1 MUFU / 2 items)
//  - linear part hoisted:  logit = x1*A + x2*B + x3*D + E + sum_j w2h_j z_j th_j
//    where A = sum_j w2h_j w0_j, etc. (block-constant warp reduction)
//  - running max fused into logit phase; float4 sum pass
// ---------------------------------------------------------------------------
__global__ __launch_bounds__(NTHREADS, 4)
void bias_bert_kernel(const int* __restrict__ seq_raw,
                      const int* __restrict__ lab_raw,
                      const float* __restrict__ Tsrc,
                      const float* __restrict__ Tdst,
                      const float* __restrict__ pb,
                      const float* __restrict__ pn,
                      const float* __restrict__ W1,
                      const float* __restrict__ b1,
                      const float* __restrict__ W2,
                      const float* __restrict__ b2,
                      float* __restrict__ out)
{
    __shared__ __align__(16) float slog[NITEMS];
    __shared__ float sw0[32], sw1[32], swr[32], sb1[32], sw2h[32];
    __shared__ float sABDE[4];
    __shared__ float swarp[8];
    __shared__ float sM;
    __shared__ int   stok[3];              // src, dst, label

    const int pos = blockIdx.x;
    const int b   = pos >> 7;
    const int t   = pos & (SEQLEN - 1);
    const int tid = threadIdx.x;

    if (tid < 32) {
        float a0 = W1[tid];
        float a1 = W1[32 + tid];
        float ar = W1[64 + tid];
        float ab = b1[tid];
        float a2 = 0.5f * W2[tid];         // fold the gelu 0.5 into w2
        sw0[tid] = a0;  sw1[tid] = a1;  swr[tid] = ar;
        sb1[tid] = ab;  sw2h[tid] = a2;

        // block-constant linear-part coefficients
        float rA = a2 * a0, rB = a2 * a1, rD = a2 * ar, rE = a2 * ab;
        #pragma unroll
        for (int o = 16; o > 0; o >>= 1) {
            rA += __shfl_xor_sync(0xffffffffu, rA, o);
            rB += __shfl_xor_sync(0xffffffffu, rB, o);
            rD += __shfl_xor_sync(0xffffffffu, rD, o);
            rE += __shfl_xor_sync(0xffffffffu, rE, o);
        }

        // int64-vs-int32 detection: probe 32 "high words" of each array.
        int hs = seq_raw[2 * tid + 1];
        int hl = lab_raw[2 * tid + 1];
        unsigned bal = __ballot_sync(0xffffffffu,
                                     (hs != 0 && hs != -1) || (hl != 0 && hl != -1));
        if (tid == 0) {
            sABDE[0] = rA; sABDE[1] = rB; sABDE[2] = rD;
            sABDE[3] = rE + b2[0];
            int stride = (bal != 0) ? 1 : 2;       // int32 : int64
            int base   = b * SEQLEN + t;
            int src = (t == 0)          ? PADTOK : max(seq_raw[(base - 1) * stride], 0);
            int dst = (t == SEQLEN - 1) ? PADTOK : max(seq_raw[(base + 1) * stride], 0);
            stok[0] = src;
            stok[1] = dst;
            stok[2] = lab_raw[base * stride];
        }
    }
    __syncthreads();

    const float* rs = Tsrc + (size_t)stok[0] * VOCABN;
    const float* rd = Tdst + (size_t)stok[1] * VOCABN;
    const int label = stok[2];
    const float cA = sABDE[0], cB = sABDE[1], cD = sABDE[2], cE = sABDE[3];

    // packed fp16 gelu constants
    unsigned CAh, CBh;
    F32x2_TO_H2(CAh, 0.0356774081f, 0.0356774081f);
    F32x2_TO_H2(CBh, 0.7978845608f, 0.7978845608f);

    float m = -3.0e38f;    // running max, fused into logit phase

    // ---- compute logits: 4 pairs (8 items) per thread per tile -----------
    for (int base = 0; base < NITEMS; base += NTHREADS * 8) {
        float x1a[4], x1b[4], x2a[4], x2b[4], x3a[4], x3b[4];
        float accl[4], acch[4];
        #pragma unroll
        for (int p = 0; p < 4; p++) {
            int v0 = base + (2 * p)     * NTHREADS + tid;
            int v1 = base + (2 * p + 1) * NTHREADS + tid;
            bool a0 = v0 < NITEMS, a1 = v1 < NITEMS;
            float d0v = a0 ? pb[v0] : 1.0f;
            float d1v = a1 ? pb[v1] : 1.0f;
            float ip0 = (d0v != 0.0f) ? rcp_fast(d0v) : 0.0f;   // div_no_nan
            float ip1 = (d1v != 0.0f) ? rcp_fast(d1v) : 0.0f;
            x1a[p] = a0 ? rs[v0] * ip0 : 0.0f;
            x1b[p] = a1 ? rs[v1] * ip1 : 0.0f;
            x2a[p] = a0 ? rd[v0] * ip0 : 0.0f;
            x2b[p] = a1 ? rd[v1] * ip1 : 0.0f;
            x3a[p] = a0 ? pn[v0] : 0.0f;
            x3b[p] = a1 ? pn[v1] : 0.0f;
            // hoisted linear part (includes b2 via cE)
            accl[p] = fmaf(x1a[p], cA, fmaf(x2a[p], cB, fmaf(x3a[p], cD, cE)));
            acch[p] = fmaf(x1b[p], cA, fmaf(x2b[p], cB, fmaf(x3b[p], cD, cE)));
        }
        #pragma unroll 4
        for (int j = 0; j < 32; j++) {
            float w0s = sw0[j], w1s = sw1[j], wrs = swr[j];
            float bbs = sb1[j], w2s = sw2h[j];
            #pragma unroll
            for (int p = 0; p < 4; p++) {
                // z in fp32 (exact)
                float zl = fmaf(x1a[p], w0s, fmaf(x2a[p], w1s, fmaf(x3a[p], wrs, bbs)));
                float zh = fmaf(x1b[p], w0s, fmaf(x2b[p], w1s, fmaf(x3b[p], wrs, bbs)));
                // cubic + tanh + z*th in f16x2
                unsigned zp, z2, wv, wz, th, sv;
                F32x2_TO_H2(zp, zh, zl);        // lo=zl, hi=zh
                HMUL2(z2, zp, zp);
                HFMA2(wv, CAh, z2, CBh);
                HMUL2(wz, wv, zp);
                HTANH2(th, wz);
                HMUL2(sv, zp, th);              // z * tanh(c(z))
                float s0, s1;
                H2_TO_F32x2(s0, s1, sv);
                // fp32 accumulate
                accl[p] = fmaf(w2s, s0, accl[p]);
                acch[p] = fmaf(w2s, s1, acch[p]);
            }
        }
        #pragma unroll
        for (int p = 0; p < 4; p++) {
            int v0 = base + (2 * p)     * NTHREADS + tid;
            int v1 = base + (2 * p + 1) * NTHREADS + tid;
            if (v0 < NITEMS) { slog[v0] = accl[p]; m = fmaxf(m, accl[p]); }
            if (v1 < NITEMS) { slog[v1] = acch[p]; m = fmaxf(m, acch[p]); }
        }
    }

    // ---- block max (m already holds thread-local max) --------------------
    #pragma unroll
    for (int o = 16; o > 0; o >>= 1) m = fmaxf(m, __shfl_xor_sync(0xffffffffu, m, o));
    if ((tid & 31) == 0) swarp[tid >> 5] = m;
    __syncthreads();                         // also covers slog visibility
    if (tid == 0) {
        float mm = swarp[0];
        #pragma unroll
        for (int i = 1; i < 8; i++) mm = fmaxf(mm, swarp[i]);
        sM = mm;
    }
    __syncthreads();
    const float M = sM;

    // ---- sum pass: float4 reads (NITEMS % 4 == 0) ------------------------
    float s = 0.0f;
    const float4* slog4 = (const float4*)slog;
    for (int v = tid; v < NITEMS / 4; v += NTHREADS) {
        float4 q = slog4[v];
        s += __expf(q.x - M) + __expf(q.y - M)
           + __expf(q.z - M) + __expf(q.w - M);
    }
    #pragma unroll
    for (int o = 16; o > 0; o >>= 1) s += __shfl_xor_sync(0xffffffffu, s, o);
    __syncthreads();                         // protect swarp reuse
    if ((tid & 31) == 0) swarp[tid >> 5] = s;
    __syncthreads();

    if (tid == 0) {
        float ss = 0.0f;
        #pragma unroll
        for (int i = 0; i < 8; i++) ss += swarp[i];
        bool valid = (label != -100);
        int  li = min(max(label, 0), NITEMS - 1);
        float ce = logf(ss) + M - slog[li];
        out[pos] = valid ? ce : 0.0f;
    }
}

// ---------------------------------------------------------------------------
// Launch: inputs per metadata order
//  0 masked_sequences  1 labels  2 transitions_src  3 transitions_dst
//  4 pop_biases  5 pop_biases_norm  6 W1  7 b1  8 W2  9 b2
// ---------------------------------------------------------------------------
extern "C" void kernel_launch(void* const* d_in, const int* in_sizes, int n_in,
                              void* d_out, int out_size)
{
    const int*   seq  = (const int*)d_in[0];
    const int*   lab  = (const int*)d_in[1];
    const float* Tsrc = (const float*)d_in[2];
    const float* Tdst = (const float*)d_in[3];
    const float* pb   = (const float*)d_in[4];
    const float* pn   = (const float*)d_in[5];
    const float* W1   = (const float*)d_in[6];
    const float* b1   = (const float*)d_in[7];
    const float* W2   = (const float*)d_in[8];
    const float* b2   = (const float*)d_in[9];

    bias_bert_kernel<<<NPOS, NTHREADS>>>(seq, lab, Tsrc, Tdst, pb, pn,
                                         W1, b1, W2, b2, (float*)d_out);
}

// round 17
// speedup vs baseline: 1.2980x; 1.2980x over previous
#include <cuda_runtime.h>
#include <math.h>

#define VOCABN   10003
#define NITEMS   10000
#define PADTOK   10000
#define NPOS     512
#define SEQLEN   128
#define NTHREADS 256

// ---------------------------------------------------------------------------
// helpers
// ---------------------------------------------------------------------------
__device__ __forceinline__ float rcp_fast(float x)
{
    float y;
    asm("rcp.approx.f32 %0, %1;" : "=f"(y) : "f"(x));
    return y;
}

// pack two f32 -> f16x2 (d.hi = hi, d.lo = lo)
#define F32x2_TO_H2(d, hi, lo) \
    asm("cvt.rn.f16x2.f32 %0, %1, %2;" : "=r"(d) : "f"(hi), "f"(lo))

// unpack f16x2 -> two f32 (s0 = lo, s1 = hi)
#define H2_TO_F32x2(s0, s1, h) \
    asm("{\n\t.reg .b16 lo, hi;\n\t" \
        "mov.b32 {lo, hi}, %2;\n\t" \
        "cvt.f32.f16 %0, lo;\n\t" \
        "cvt.f32.f16 %1, hi;\n\t}" \
        : "=f"(s0), "=f"(s1) : "r"(h))

#define HMUL2(d, a, b) \
    asm("mul.f16x2 %0, %1, %2;" : "=r"(d) : "r"(a), "r"(b))
#define HFMA2(d, a, b, c) \
    asm("fma.rn.f16x2 %0, %1, %2, %3;" : "=r"(d) : "r"(a), "r"(b), "r"(c))
#define HADD2(d, a, b) \
    asm("add.f16x2 %0, %1, %2;" : "=r"(d) : "r"(a), "r"(b))
#define HTANH2(d, a) \
    asm("tanh.approx.f16x2 %0, %1;" : "=r"(d) : "r"(a))

// ---------------------------------------------------------------------------
// Fully fused kernel: one block per (b, t) position.
//  - in-block int64/int32 token decode (warp-0 ballot probe)
//  - inline 1/pop_biases via rcp.approx (+ div_no_nan zero guard)
//  - x packed to f16x2 ONCE per tile; entire per-j chain in f16x2
//    (8 rt2 fma-pipe ops + 1 tanh.f16x2 MUFU per pair per j — no per-j cvt)
//  - linear part hoisted in exact fp32:
//      logit = x1*A + x2*B + x3*D + E + sum_j w2h_j * z_j * tanh(c(z_j))
//  - even/odd-j split h2 accumulators -> fp32 once per tile
//  - running max fused into logit phase; float4 sum pass
// ---------------------------------------------------------------------------
__global__ __launch_bounds__(NTHREADS, 4)
void bias_bert_kernel(const int* __restrict__ seq_raw,
                      const int* __restrict__ lab_raw,
                      const float* __restrict__ Tsrc,
                      const float* __restrict__ Tdst,
                      const float* __restrict__ pb,
                      const float* __restrict__ pn,
                      const float* __restrict__ W1,
                      const float* __restrict__ b1,
                      const float* __restrict__ W2,
                      const float* __restrict__ b2,
                      float* __restrict__ out)
{
    __shared__ __align__(16) float slog[NITEMS];
    __shared__ unsigned sw0h[32], sw1h[32], swrh[32], sb1h[32], sw2h2[32];
    __shared__ float sABDE[4];
    __shared__ float swarp[8];
    __shared__ float sM;
    __shared__ int   stok[3];              // src, dst, label

    const int pos = blockIdx.x;
    const int b   = pos >> 7;
    const int t   = pos & (SEQLEN - 1);
    const int tid = threadIdx.x;

    if (tid < 32) {
        float a0 = W1[tid];
        float a1 = W1[32 + tid];
        float ar = W1[64 + tid];
        float ab = b1[tid];
        float a2 = 0.5f * W2[tid];         // fold the gelu 0.5 into w2
        unsigned h;
        F32x2_TO_H2(h, a0, a0);  sw0h[tid]  = h;
        F32x2_TO_H2(h, a1, a1);  sw1h[tid]  = h;
        F32x2_TO_H2(h, ar, ar);  swrh[tid]  = h;
        F32x2_TO_H2(h, ab, ab);  sb1h[tid]  = h;
        F32x2_TO_H2(h, a2, a2);  sw2h2[tid] = h;

        // block-constant linear-part coefficients (exact fp32)
        float rA = a2 * a0, rB = a2 * a1, rD = a2 * ar, rE = a2 * ab;
        #pragma unroll
        for (int o = 16; o > 0; o >>= 1) {
            rA += __shfl_xor_sync(0xffffffffu, rA, o);
            rB += __shfl_xor_sync(0xffffffffu, rB, o);
            rD += __shfl_xor_sync(0xffffffffu, rD, o);
            rE += __shfl_xor_sync(0xffffffffu, rE, o);
        }

        // int64-vs-int32 detection: probe 32 "high words" of each array.
        int hs = seq_raw[2 * tid + 1];
        int hl = lab_raw[2 * tid + 1];
        unsigned bal = __ballot_sync(0xffffffffu,
                                     (hs != 0 && hs != -1) || (hl != 0 && hl != -1));
        if (tid == 0) {
            sABDE[0] = rA; sABDE[1] = rB; sABDE[2] = rD;
            sABDE[3] = rE + b2[0];
            int stride = (bal != 0) ? 1 : 2;       // int32 : int64
            int base   = b * SEQLEN + t;
            int src = (t == 0)          ? PADTOK : max(seq_raw[(base - 1) * stride], 0);
            int dst = (t == SEQLEN - 1) ? PADTOK : max(seq_raw[(base + 1) * stride], 0);
            stok[0] = src;
            stok[1] = dst;
            stok[2] = lab_raw[base * stride];
        }
    }
    __syncthreads();

    const float* rs = Tsrc + (size_t)stok[0] * VOCABN;
    const float* rd = Tdst + (size_t)stok[1] * VOCABN;
    const int label = stok[2];
    const float cA = sABDE[0], cB = sABDE[1], cD = sABDE[2], cE = sABDE[3];

    // packed fp16 gelu constants
    unsigned CAh, CBh;
    F32x2_TO_H2(CAh, 0.0356774081f, 0.0356774081f);
    F32x2_TO_H2(CBh, 0.7978845608f, 0.7978845608f);

    float m = -3.0e38f;    // running max, fused into logit phase

    // ---- compute logits: 4 pairs (8 items) per thread per tile -----------
    for (int base = 0; base < NITEMS; base += NTHREADS * 8) {
        unsigned x1h[4], x2h[4], x3h[4], acc0[4], acc1[4];
        float linl[4], linh[4];
        #pragma unroll
        for (int p = 0; p < 4; p++) {
            int v0 = base + (2 * p)     * NTHREADS + tid;
            int v1 = base + (2 * p + 1) * NTHREADS + tid;
            bool a0 = v0 < NITEMS, a1 = v1 < NITEMS;
            float d0v = a0 ? pb[v0] : 1.0f;
            float d1v = a1 ? pb[v1] : 1.0f;
            float ip0 = (d0v != 0.0f) ? rcp_fast(d0v) : 0.0f;   // div_no_nan
            float ip1 = (d1v != 0.0f) ? rcp_fast(d1v) : 0.0f;
            float x1a = a0 ? rs[v0] * ip0 : 0.0f;
            float x1b = a1 ? rs[v1] * ip1 : 0.0f;
            float x2a = a0 ? rd[v0] * ip0 : 0.0f;
            float x2b = a1 ? rd[v1] * ip1 : 0.0f;
            float x3a = a0 ? pn[v0] : 0.0f;
            float x3b = a1 ? pn[v1] : 0.0f;
            // hoisted linear part (includes b2 via cE), exact fp32
            linl[p] = fmaf(x1a, cA, fmaf(x2a, cB, fmaf(x3a, cD, cE)));
            linh[p] = fmaf(x1b, cA, fmaf(x2b, cB, fmaf(x3b, cD, cE)));
            // pack once per tile (lo = item v0, hi = item v1)
            F32x2_TO_H2(x1h[p], x1b, x1a);
            F32x2_TO_H2(x2h[p], x2b, x2a);
            F32x2_TO_H2(x3h[p], x3b, x3a);
            acc0[p] = 0u;
            acc1[p] = 0u;
        }
        #pragma unroll 4
        for (int j = 0; j < 32; j++) {
            unsigned w0h = sw0h[j], w1h = sw1h[j], wrh = swrh[j];
            unsigned bbh = sb1h[j], w2h = sw2h2[j];
            #pragma unroll
            for (int p = 0; p < 4; p++) {
                unsigned z, z2, w, wz, th, s;
                HFMA2(z, x3h[p], wrh, bbh);
                HFMA2(z, x2h[p], w1h, z);
                HFMA2(z, x1h[p], w0h, z);
                HMUL2(z2, z, z);
                HFMA2(w, CAh, z2, CBh);
                HMUL2(wz, w, z);
                HTANH2(th, wz);
                HMUL2(s, z, th);               // z * tanh(c(z))
                if (j & 1) { HFMA2(acc1[p], w2h, s, acc1[p]); }
                else       { HFMA2(acc0[p], w2h, s, acc0[p]); }
            }
        }
        #pragma unroll
        for (int p = 0; p < 4; p++) {
            int v0 = base + (2 * p)     * NTHREADS + tid;
            int v1 = base + (2 * p + 1) * NTHREADS + tid;
            unsigned at;
            HADD2(at, acc0[p], acc1[p]);
            float s0, s1;
            H2_TO_F32x2(s0, s1, at);
            float l0 = linl[p] + s0;
            float l1 = linh[p] + s1;
            if (v0 < NITEMS) { slog[v0] = l0; m = fmaxf(m, l0); }
            if (v1 < NITEMS) { slog[v1] = l1; m = fmaxf(m, l1); }
        }
    }

    // ---- block max (m already holds thread-local max) --------------------
    #pragma unroll
    for (int o = 16; o > 0; o >>= 1) m = fmaxf(m, __shfl_xor_sync(0xffffffffu, m, o));
    if ((tid & 31) == 0) swarp[tid >> 5] = m;
    __syncthreads();                         // also covers slog visibility
    if (tid == 0) {
        float mm = swarp[0];
        #pragma unroll
        for (int i = 1; i < 8; i++) mm = fmaxf(mm, swarp[i]);
        sM = mm;
    }
    __syncthreads();
    const float M = sM;

    // ---- sum pass: float4 reads (NITEMS % 4 == 0) ------------------------
    float s = 0.0f;
    const float4* slog4 = (const float4*)slog;
    for (int v = tid; v < NITEMS / 4; v += NTHREADS) {
        float4 q = slog4[v];
        s += __expf(q.x - M) + __expf(q.y - M)
           + __expf(q.z - M) + __expf(q.w - M);
    }
    #pragma unroll
    for (int o = 16; o > 0; o >>= 1) s += __shfl_xor_sync(0xffffffffu, s, o);
    __syncthreads();                         // protect swarp reuse
    if ((tid & 31) == 0) swarp[tid >> 5] = s;
    __syncthreads();

    if (tid == 0) {
        float ss = 0.0f;
        #pragma unroll
        for (int i = 0; i < 8; i++) ss += swarp[i];
        bool valid = (label != -100);
        int  li = min(max(label, 0), NITEMS - 1);
        float ce = logf(ss) + M - slog[li];
        out[pos] = valid ? ce : 0.0f;
    }
}

// ---------------------------------------------------------------------------
// Launch: inputs per metadata order
//  0 masked_sequences  1 labels  2 transitions_src  3 transitions_dst
//  4 pop_biases  5 pop_biases_norm  6 W1  7 b1  8 W2  9 b2
// ---------------------------------------------------------------------------
extern "C" void kernel_launch(void* const* d_in, const int* in_sizes, int n_in,
                              void* d_out, int out_size)
{
    const int*   seq  = (const int*)d_in[0];
    const int*   lab  = (const int*)d_in[1];
    const float* Tsrc = (const float*)d_in[2];
    const float* Tdst = (const float*)d_in[3];
    const float* pb   = (const float*)d_in[4];
    const float* pn   = (const float*)d_in[5];
    const float* W1   = (const float*)d_in[6];
    const float* b1   = (const float*)d_in[7];
    const float* W2   = (const float*)d_in[8];
    const float* b2   = (const float*)d_in[9];

    bias_bert_kernel<<<NPOS, NTHREADS>>>(seq, lab, Tsrc, Tdst, pb, pn,
                                         W1, b1, W2, b2, (float*)d_out);
}